// round 10
// baseline (speedup 1.0000x reference)
#include <cuda_runtime.h>
#include <stdint.h>
#include <math.h>

// ---------------------------------------------------------------------------
// EncoderLayer: B=32, S=512, D=1024, H=16, dk=64, F=4096
// Round 10: dual-pipe GEMM. mma.sync on sm_103a is a slow legacy path
// (~70 TF/s cap, confirmed over rounds 3/5/8/9), so half the CTAs run the
// proven tf32-HMMA engine (tensor pipe) and half run a packed fma.rn.f32x2
// engine (FMA pipe) on the same tf32-rounded operands. Type is chosen per
// blockIdx so co-resident CTAs (bid, bid+148) use opposite pipes.
// Attention (512 thr) + LN + rna-preround unchanged from round 9.
// ---------------------------------------------------------------------------

#define B_  32
#define S_  512
#define D_  1024
#define H_  16
#define DK_ 64
#define F_  4096
#define M_  (B_ * S_)          // 16384 rows

// -------------------- scratch (device globals; no allocs) ------------------
__device__ float g_q    [M_ * D_];
__device__ float g_k    [M_ * D_];
__device__ float g_v    [M_ * D_];
__device__ float g_ctx  [M_ * D_];   // rounded (feeds Wo GEMM)
__device__ float g_attn [M_ * D_];
__device__ float g_out1 [M_ * D_];
__device__ float g_out1r[M_ * D_];   // rounded (feeds FFN1)
__device__ float g_ffn  [M_ * D_];
__device__ float g_h    [M_ * F_];   // rounded (feeds FFN2)
__device__ float g_xr   [M_ * D_];   // rounded x
__device__ float g_wqr  [D_ * D_];
__device__ float g_wkr  [D_ * D_];
__device__ float g_wvr  [D_ * D_];
__device__ float g_wor  [D_ * D_];
__device__ float g_w1r  [D_ * F_];
__device__ float g_w2r  [F_ * D_];

// ---------------------------------------------------------------------------
// Helpers
// ---------------------------------------------------------------------------
__device__ __forceinline__ float gelu_erf_f(float x) {
    return 0.5f * x * (1.0f + erff(x * 0.70710678118654752f));
}
__device__ __forceinline__ float tf32r(float f) {   // rna-round to tf32
    uint32_t u;
    asm("cvt.rna.tf32.f32 %0, %1;" : "=r"(u) : "f"(f));
    return __uint_as_float(u);
}
__device__ __forceinline__ uint32_t smem_u32(const void* p) {
    uint32_t a;
    asm("{ .reg .u64 t; cvta.to.shared.u64 t, %1; cvt.u32.u64 %0, t; }"
        : "=r"(a) : "l"(p));
    return a;
}
__device__ __forceinline__ void cp16(uint32_t s, const void* g) {
    asm volatile("cp.async.cg.shared.global [%0], [%1], 16;" :: "r"(s), "l"(g));
}
__device__ __forceinline__ void cp_commit() {
    asm volatile("cp.async.commit_group;" ::: "memory");
}
template <int N>
__device__ __forceinline__ void cp_wait() {
    asm volatile("cp.async.wait_group %0;" :: "n"(N) : "memory");
}
__device__ __forceinline__ void mma_tf32(float c[4],
                                         uint32_t a0, uint32_t a1, uint32_t a2, uint32_t a3,
                                         uint32_t b0, uint32_t b1) {
    asm volatile(
        "mma.sync.aligned.m16n8k8.row.col.f32.tf32.tf32.f32 "
        "{%0,%1,%2,%3}, {%4,%5,%6,%7}, {%8,%9}, {%0,%1,%2,%3};\n"
        : "+f"(c[0]), "+f"(c[1]), "+f"(c[2]), "+f"(c[3])
        : "r"(a0), "r"(a1), "r"(a2), "r"(a3), "r"(b0), "r"(b1));
}
// packed fp32x2 FMA (Blackwell base-arch)
__device__ __forceinline__ unsigned long long pack2(float x) {
    unsigned long long r;
    asm("mov.b64 %0, {%1, %1};" : "=l"(r) : "f"(x));
    return r;
}
__device__ __forceinline__ void fma2(unsigned long long& d,
                                     unsigned long long a, unsigned long long b) {
    asm("fma.rn.f32x2 %0, %1, %2, %0;" : "+l"(d) : "l"(a), "l"(b));
}
__device__ __forceinline__ void unpack2(float& lo, float& hi, unsigned long long v) {
    asm("mov.b64 {%0, %1}, %2;" : "=f"(lo), "=f"(hi) : "l"(v));
}

// ---------------------------------------------------------------------------
// Preprocess: Y = tf32_rna(X)
// ---------------------------------------------------------------------------
__global__ void rnd_kernel(const float* __restrict__ X, float* __restrict__ Y,
                           int n4) {
    int i = blockIdx.x * blockDim.x + threadIdx.x;
    if (i < n4) {
        float4 v = ((const float4*)X)[i];
        v.x = tf32r(v.x); v.y = tf32r(v.y); v.z = tf32r(v.z); v.w = tf32r(v.w);
        ((float4*)Y)[i] = v;
    }
}

// ---------------------------------------------------------------------------
// Dual-pipe GEMM: C[M,N] = act(A[M,K] @ W[K,N] + bias[N])
// CTA 128x128, BK=16 per stage, 4 cp.async stages, 256 threads.
// Engine per CTA: (bx>>2)&1 == 0 -> tf32 HMMA (tensor pipe)
//                 (bx>>2)&1 == 1 -> packed f32x2 FFMA (FMA pipe)
// Smem: As[stage][128][20] fp32 row-major, Bs[stage][16][136] fp32.
// ---------------------------------------------------------------------------
#define ASTR 20
#define BSTR 136
#define STG_FLT (128 * ASTR + 16 * BSTR)   // 4736
#define GEMM_SMEM (4 * STG_FLT * 4)        // 75776 bytes

template <int ACT, int ROUND>
__global__ __launch_bounds__(256, 2) void dual_gemm(
    const float* __restrict__ A, const float* __restrict__ W,
    const float* __restrict__ bias, float* __restrict__ C,
    int N, int K)
{
    extern __shared__ float sm[];

    const int tid = threadIdx.x;
    const int bx = blockIdx.x, by = blockIdx.y;

    // cp.async producer mapping (shared by both engines)
    const int ar = tid >> 1, ak = (tid & 1) * 8;
    const int bk = tid >> 4, bn = (tid & 15) * 8;
    const float* Ag = A + (size_t)(by * 128 + ar) * K + ak;
    const float* Bg = W + (size_t)bk * N + bx * 128 + bn;
    uint32_t sA0 = smem_u32(sm) + (uint32_t)(ar * ASTR + ak) * 4u;
    uint32_t sB0 = smem_u32(sm) + (uint32_t)(128 * ASTR + bk * BSTR + bn) * 4u;

    auto issue = [&](int kt) {
        const uint32_t so = (uint32_t)(kt & 3) * (STG_FLT * 4u);
        const float* ap = Ag + kt * 16;
        const float* bp = Bg + (size_t)(kt * 16) * N;
        cp16(sA0 + so,      ap);
        cp16(sA0 + so + 16, ap + 4);
        cp16(sB0 + so,      bp);
        cp16(sB0 + so + 16, bp + 4);
        cp_commit();
    };

    const int nk = K >> 4;

    if (((bx >> 2) & 1) == 0) {
        // ================= tensor-pipe engine (tf32 HMMA) =================
        const int wid = tid >> 5, lane = tid & 31;
        const int wm = (wid >> 2) * 64;
        const int wn = (wid & 3) * 32;
        const int g  = lane >> 2;
        const int q  = lane & 3;

        float acc[4][4][4];
        #pragma unroll
        for (int mi = 0; mi < 4; mi++)
            #pragma unroll
            for (int nj = 0; nj < 4; nj++)
                #pragma unroll
                for (int r = 0; r < 4; r++) acc[mi][nj][r] = 0.f;

        issue(0); issue(1); issue(2);

        for (int kt = 0; kt < nk; ++kt) {
            cp_wait<2>();
            __syncthreads();
            if (kt + 3 < nk) issue(kt + 3);

            const uint32_t* As32 = (const uint32_t*)(sm + (kt & 3) * STG_FLT);
            const uint32_t* Bs32 = As32 + 128 * ASTR;

            #pragma unroll
            for (int ks = 0; ks < 2; ++ks) {
                const int k0 = ks * 8;
                uint32_t a[4][4], b[4][2];
                #pragma unroll
                for (int mi = 0; mi < 4; mi++) {
                    const int m0 = wm + mi * 16 + g;
                    a[mi][0] = As32[(m0    ) * ASTR + k0 + q];
                    a[mi][1] = As32[(m0 + 8) * ASTR + k0 + q];
                    a[mi][2] = As32[(m0    ) * ASTR + k0 + q + 4];
                    a[mi][3] = As32[(m0 + 8) * ASTR + k0 + q + 4];
                }
                #pragma unroll
                for (int nj = 0; nj < 4; nj++) {
                    const int n0 = wn + nj * 8 + g;
                    b[nj][0] = Bs32[(k0 + q    ) * BSTR + n0];
                    b[nj][1] = Bs32[(k0 + q + 4) * BSTR + n0];
                }
                #pragma unroll
                for (int mi = 0; mi < 4; mi++)
                    #pragma unroll
                    for (int nj = 0; nj < 4; nj++)
                        mma_tf32(acc[mi][nj], a[mi][0], a[mi][1], a[mi][2], a[mi][3],
                                 b[nj][0], b[nj][1]);
            }
        }

        #pragma unroll
        for (int nj = 0; nj < 4; nj++) {
            const int col = bx * 128 + wn + nj * 8 + 2 * q;
            const float2 bb = *(const float2*)&bias[col];
            #pragma unroll
            for (int mi = 0; mi < 4; mi++) {
                const int row0 = by * 128 + wm + mi * 16 + g;
                float2 o0, o1;
                o0.x = acc[mi][nj][0] + bb.x;
                o0.y = acc[mi][nj][1] + bb.y;
                o1.x = acc[mi][nj][2] + bb.x;
                o1.y = acc[mi][nj][3] + bb.y;
                if (ACT == 1) {
                    o0.x = gelu_erf_f(o0.x); o0.y = gelu_erf_f(o0.y);
                    o1.x = gelu_erf_f(o1.x); o1.y = gelu_erf_f(o1.y);
                }
                if (ROUND == 1) {
                    o0.x = tf32r(o0.x); o0.y = tf32r(o0.y);
                    o1.x = tf32r(o1.x); o1.y = tf32r(o1.y);
                }
                *(float2*)&C[(size_t)row0 * N + col]       = o0;
                *(float2*)&C[(size_t)(row0 + 8) * N + col] = o1;
            }
        }
    } else {
        // ================= FMA-pipe engine (packed f32x2) =================
        // thread microtile 8x8: ty = tid>>4 (16 x 8 rows), tx = tid&15 (16 x 8 cols)
        const int ty = tid >> 4, tx = tid & 15;

        unsigned long long acc[8][4];
        #pragma unroll
        for (int i = 0; i < 8; i++)
            #pragma unroll
            for (int j = 0; j < 4; j++) acc[i][j] = 0ull;

        issue(0); issue(1); issue(2);

        for (int kt = 0; kt < nk; ++kt) {
            cp_wait<2>();
            __syncthreads();
            if (kt + 3 < nk) issue(kt + 3);

            const float* As = sm + (kt & 3) * STG_FLT;
            const float* Bs = As + 128 * ASTR;

            #pragma unroll 4
            for (int k = 0; k < 16; ++k) {
                unsigned long long ap[8];
                #pragma unroll
                for (int i = 0; i < 8; i++)
                    ap[i] = pack2(As[(ty * 8 + i) * ASTR + k]);
                unsigned long long bv[4];
                #pragma unroll
                for (int j = 0; j < 4; j++)
                    bv[j] = *(const unsigned long long*)&Bs[k * BSTR + tx * 8 + 2 * j];
                #pragma unroll
                for (int i = 0; i < 8; i++)
                    #pragma unroll
                    for (int j = 0; j < 4; j++)
                        fma2(acc[i][j], ap[i], bv[j]);
            }
        }

        const int col0 = bx * 128 + tx * 8;
        #pragma unroll
        for (int i = 0; i < 8; i++) {
            const int row = by * 128 + ty * 8 + i;
            float o[8];
            #pragma unroll
            for (int j = 0; j < 4; j++)
                unpack2(o[2 * j], o[2 * j + 1], acc[i][j]);
            #pragma unroll
            for (int j = 0; j < 8; j++) {
                float v = o[j] + bias[col0 + j];
                if (ACT == 1) v = gelu_erf_f(v);
                if (ROUND == 1) v = tf32r(v);
                o[j] = v;
            }
            *(float4*)&C[(size_t)row * N + col0]     = *(float4*)&o[0];
            *(float4*)&C[(size_t)row * N + col0 + 4] = *(float4*)&o[4];
        }
    }
}

// ---------------------------------------------------------------------------
// Fused attention: grid (S/64, H, B), 512 threads (16 warps). (round-9)
// ---------------------------------------------------------------------------
#define SC_STRIDE 516
#define QK_STRIDE 68

__global__ __launch_bounds__(512) void attention_kernel(
    const float* __restrict__ Q, const float* __restrict__ K,
    const float* __restrict__ V, const int* __restrict__ mask,
    const float* __restrict__ adj, float* __restrict__ ctx)
{
    extern __shared__ float smem[];
    float* sc = smem;                       // 64 * 516
    float* qs = sc + 64 * SC_STRIDE;        // 64 * 68
    float* kv = qs + 64 * QK_STRIDE;        // 64 * 68

    const int t  = threadIdx.x;
    const int qt = blockIdx.x, h = blockIdx.y, b = blockIdx.z;
    const int qbase = b * S_ + qt * 64;

    #pragma unroll
    for (int i = 0; i < 2; i++) {
        int lin = t + i * 512;
        int r = lin >> 4, c4 = (lin & 15) << 2;
        float4 qv = *(const float4*)&Q[(size_t)(qbase + r) * D_ + h * DK_ + c4];
        qv.x *= 0.125f; qv.y *= 0.125f; qv.z *= 0.125f; qv.w *= 0.125f;
        *(float4*)&qs[r * QK_STRIDE + c4] = qv;
    }

    const int qi  = t >> 3;          // 0..63
    const int kj0 = (t & 7) << 3;    // 0,8,..,56
    const int qg  = qt * 64 + qi;

    for (int kt = 0; kt < 8; ++kt) {
        __syncthreads();
        #pragma unroll
        for (int i = 0; i < 2; i++) {
            int lin = t + i * 512;
            int r = lin >> 4, c4 = (lin & 15) << 2;
            float4 kk = *(const float4*)&K[(size_t)(b * S_ + kt * 64 + r) * D_ + h * DK_ + c4];
            kv[(c4 + 0) * QK_STRIDE + r] = kk.x;
            kv[(c4 + 1) * QK_STRIDE + r] = kk.y;
            kv[(c4 + 2) * QK_STRIDE + r] = kk.z;
            kv[(c4 + 3) * QK_STRIDE + r] = kk.w;
        }
        __syncthreads();

        float acc[8];
        #pragma unroll
        for (int j = 0; j < 8; j++) acc[j] = 0.f;

        #pragma unroll
        for (int d = 0; d < 64; ++d) {
            float qv = qs[qi * QK_STRIDE + d];
            const float4* kr = (const float4*)&kv[d * QK_STRIDE + kj0];
            float4 k0 = kr[0], k1 = kr[1];
            acc[0] += qv * k0.x; acc[1] += qv * k0.y; acc[2] += qv * k0.z; acc[3] += qv * k0.w;
            acc[4] += qv * k1.x; acc[5] += qv * k1.y; acc[6] += qv * k1.z; acc[7] += qv * k1.w;
        }

        const float* adjr = &adj[((size_t)(b * S_ + qg)) * S_ + kt * 64 + kj0];
        const int*   mr   = &mask[b * S_ + kt * 64 + kj0];
        float*       scr  = &sc[qi * SC_STRIDE + kt * 64 + kj0];
        #pragma unroll
        for (int j = 0; j < 8; j++)
            scr[j] = acc[j] + (float)mr[j] * -1e9f + adjr[j];
    }
    __syncthreads();

    {
        const int warp = t >> 5, lane = t & 31;
        for (int row = warp; row < 64; row += 16) {
            float* r = &sc[row * SC_STRIDE];
            float mx = -3.0e38f;
            #pragma unroll
            for (int i = 0; i < 16; i++) mx = fmaxf(mx, r[lane + 32 * i]);
            #pragma unroll
            for (int o = 16; o; o >>= 1) mx = fmaxf(mx, __shfl_xor_sync(0xffffffffu, mx, o));
            float e[16], sum = 0.f;
            #pragma unroll
            for (int i = 0; i < 16; i++) { e[i] = __expf(r[lane + 32 * i] - mx); sum += e[i]; }
            #pragma unroll
            for (int o = 16; o; o >>= 1) sum += __shfl_xor_sync(0xffffffffu, sum, o);
            const float inv = 1.0f / sum;
            #pragma unroll
            for (int i = 0; i < 16; i++) r[lane + 32 * i] = e[i] * inv;
        }
    }

    const int dc0 = kj0;
    float acc[8];
    #pragma unroll
    for (int j = 0; j < 8; j++) acc[j] = 0.f;

    for (int kt = 0; kt < 8; ++kt) {
        __syncthreads();
        #pragma unroll
        for (int i = 0; i < 2; i++) {
            int lin = t + i * 512;
            int r = lin >> 4, c4 = (lin & 15) << 2;
            float4 vv = *(const float4*)&V[(size_t)(b * S_ + kt * 64 + r) * D_ + h * DK_ + c4];
            *(float4*)&kv[r * QK_STRIDE + c4] = vv;
        }
        __syncthreads();

        #pragma unroll
        for (int kk = 0; kk < 64; ++kk) {
            float p = sc[qi * SC_STRIDE + kt * 64 + kk];
            const float4* vr = (const float4*)&kv[kk * QK_STRIDE + dc0];
            float4 v0 = vr[0], v1 = vr[1];
            acc[0] += p * v0.x; acc[1] += p * v0.y; acc[2] += p * v0.z; acc[3] += p * v0.w;
            acc[4] += p * v1.x; acc[5] += p * v1.y; acc[6] += p * v1.z; acc[7] += p * v1.w;
        }
    }

    float* outp = &ctx[(size_t)(qbase + qi) * D_ + h * DK_ + dc0];
    float4 o0, o1;
    o0.x = tf32r(acc[0]); o0.y = tf32r(acc[1]); o0.z = tf32r(acc[2]); o0.w = tf32r(acc[3]);
    o1.x = tf32r(acc[4]); o1.y = tf32r(acc[5]); o1.z = tf32r(acc[6]); o1.w = tf32r(acc[7]);
    *(float4*)&outp[0] = o0;
    *(float4*)&outp[4] = o1;
}

// ---------------------------------------------------------------------------
// Residual + LayerNorm; optional tf32-rounded secondary output
// ---------------------------------------------------------------------------
__device__ __forceinline__ float blockReduceSum(float val, float* shared) {
    const int lane = threadIdx.x & 31, wid = threadIdx.x >> 5;
    #pragma unroll
    for (int o = 16; o; o >>= 1) val += __shfl_xor_sync(0xffffffffu, val, o);
    __syncthreads();
    if (lane == 0) shared[wid] = val;
    __syncthreads();
    float r = shared[0];
    #pragma unroll
    for (int w = 1; w < 8; w++) r += shared[w];
    return r;
}

template <int WR>
__global__ __launch_bounds__(256) void ln_residual_kernel(
    const float* __restrict__ A, const float* __restrict__ Bm,
    const float* __restrict__ gamma, const float* __restrict__ beta,
    float* __restrict__ out, float* __restrict__ outR)
{
    __shared__ float red[8];
    const int row = blockIdx.x;
    const int tid = threadIdx.x;
    const size_t base = (size_t)row * D_;

    float v[4];
    float s = 0.f;
    #pragma unroll
    for (int i = 0; i < 4; i++) {
        int c = tid + 256 * i;
        v[i] = A[base + c] + Bm[base + c];
        s += v[i];
    }
    s = blockReduceSum(s, red);
    const float mean = s * (1.0f / (float)D_);

    float s2 = 0.f;
    #pragma unroll
    for (int i = 0; i < 4; i++) { float d = v[i] - mean; s2 += d * d; }
    s2 = blockReduceSum(s2, red);

    const float stdv = sqrtf(s2 * (1.0f / (float)(D_ - 1)));   // ddof=1
    const float inv  = 1.0f / (stdv + 1e-6f);                  // /(std+eps)

    #pragma unroll
    for (int i = 0; i < 4; i++) {
        int c = tid + 256 * i;
        float o = gamma[c] * (v[i] - mean) * inv + beta[c];
        out[base + c] = o;
        if (WR) outR[base + c] = tf32r(o);
    }
}

// ---------------------------------------------------------------------------
// launch
// ---------------------------------------------------------------------------
extern "C" void kernel_launch(void* const* d_in, const int* in_sizes, int n_in,
                              void* d_out, int out_size)
{
    const float* x    = (const float*)d_in[0];
    const int*   mask = (const int*)  d_in[1];
    const float* adj  = (const float*)d_in[2];
    const float* Wq = (const float*)d_in[4];  const float* bq = (const float*)d_in[5];
    const float* Wk = (const float*)d_in[6];  const float* bk = (const float*)d_in[7];
    const float* Wv = (const float*)d_in[8];  const float* bv = (const float*)d_in[9];
    const float* Wo = (const float*)d_in[10]; const float* bo = (const float*)d_in[11];
    const float* W1 = (const float*)d_in[12]; const float* b1 = (const float*)d_in[13];
    const float* W2 = (const float*)d_in[14]; const float* b2 = (const float*)d_in[15];
    const float* gamma = (const float*)d_in[16];
    const float* beta  = (const float*)d_in[17];
    float* out = (float*)d_out;

    float *q, *k, *v, *ctx, *attn, *out1, *out1r, *ffn, *hbuf;
    float *xr, *wqr, *wkr, *wvr, *wor, *w1r, *w2r;
    cudaGetSymbolAddress((void**)&q,     g_q);
    cudaGetSymbolAddress((void**)&k,     g_k);
    cudaGetSymbolAddress((void**)&v,     g_v);
    cudaGetSymbolAddress((void**)&ctx,   g_ctx);
    cudaGetSymbolAddress((void**)&attn,  g_attn);
    cudaGetSymbolAddress((void**)&out1,  g_out1);
    cudaGetSymbolAddress((void**)&out1r, g_out1r);
    cudaGetSymbolAddress((void**)&ffn,   g_ffn);
    cudaGetSymbolAddress((void**)&hbuf,  g_h);
    cudaGetSymbolAddress((void**)&xr,    g_xr);
    cudaGetSymbolAddress((void**)&wqr,   g_wqr);
    cudaGetSymbolAddress((void**)&wkr,   g_wkr);
    cudaGetSymbolAddress((void**)&wvr,   g_wvr);
    cudaGetSymbolAddress((void**)&wor,   g_wor);
    cudaGetSymbolAddress((void**)&w1r,   g_w1r);
    cudaGetSymbolAddress((void**)&w2r,   g_w2r);

    cudaFuncSetAttribute(dual_gemm<0,0>,
                         cudaFuncAttributeMaxDynamicSharedMemorySize, GEMM_SMEM);
    cudaFuncSetAttribute(dual_gemm<1,1>,
                         cudaFuncAttributeMaxDynamicSharedMemorySize, GEMM_SMEM);

    const int ATTN_SMEM = (64 * SC_STRIDE + 2 * 64 * QK_STRIDE) * (int)sizeof(float);
    cudaFuncSetAttribute(attention_kernel,
                         cudaFuncAttributeMaxDynamicSharedMemorySize, ATTN_SMEM);

    // ---- preprocessing: rna-round GEMM operands ----
    rnd_kernel<<<(M_ * D_ / 4 + 255) / 256, 256>>>(x,  xr,  M_ * D_ / 4);
    rnd_kernel<<<(D_ * D_ / 4 + 255) / 256, 256>>>(Wq, wqr, D_ * D_ / 4);
    rnd_kernel<<<(D_ * D_ / 4 + 255) / 256, 256>>>(Wk, wkr, D_ * D_ / 4);
    rnd_kernel<<<(D_ * D_ / 4 + 255) / 256, 256>>>(Wv, wvr, D_ * D_ / 4);
    rnd_kernel<<<(D_ * D_ / 4 + 255) / 256, 256>>>(Wo, wor, D_ * D_ / 4);
    rnd_kernel<<<(D_ * F_ / 4 + 255) / 256, 256>>>(W1, w1r, D_ * F_ / 4);
    rnd_kernel<<<(F_ * D_ / 4 + 255) / 256, 256>>>(W2, w2r, F_ * D_ / 4);

    dim3 gD(D_ / 128, M_ / 128);   // (8, 128)
    dim3 gF(F_ / 128, M_ / 128);   // (32, 128)

    // QKV projections
    dual_gemm<0,0><<<gD, 256, GEMM_SMEM>>>(xr, wqr, bq, q, D_, D_);
    dual_gemm<0,0><<<gD, 256, GEMM_SMEM>>>(xr, wkr, bk, k, D_, D_);
    dual_gemm<0,0><<<gD, 256, GEMM_SMEM>>>(xr, wvr, bv, v, D_, D_);

    // attention (fp32 compute; emits rounded ctx)
    dim3 gA(S_ / 64, H_, B_);
    attention_kernel<<<gA, 512, ATTN_SMEM>>>(q, k, v, mask, adj, ctx);

    // output projection
    dual_gemm<0,0><<<gD, 256, GEMM_SMEM>>>(ctx, wor, bo, attn, D_, D_);

    // LN1: out1 = LN(x + attn); exact + rounded
    ln_residual_kernel<1><<<M_, 256>>>(x, attn, gamma, beta, out1, out1r);

    // FFN
    dual_gemm<1,1><<<gF, 256, GEMM_SMEM>>>(out1r, w1r, b1, hbuf, F_, D_);
    dual_gemm<0,0><<<gD, 256, GEMM_SMEM>>>(hbuf, w2r, b2, ffn, D_, F_);

    // LN2: out = LN(out1 + ffn)
    ln_residual_kernel<0><<<M_, 256>>>(out1, ffn, gamma, beta, out, (float*)0);
}

// round 11
// speedup vs baseline: 1.1551x; 1.1551x over previous
#include <cuda_runtime.h>
#include <stdint.h>
#include <math.h>

// ---------------------------------------------------------------------------
// EncoderLayer: B=32, S=512, D=1024, H=16, dk=64, F=4096
// Round 11: persistent dual-pipe GEMM with GUARANTEED engine pairing.
// Grid = 296 CTAs; classic placement puts bid and bid+148 on the same SM, so
// bid<148 -> HMMA engine, bid>=148 -> FFMA engine gives 1 of each per SM.
// Static deterministic split: FFMA engine takes the last 1/4 of tiles.
// Also fixes a latent cp.async under-wait on the last two pipeline stages.
// Attention (512 thr) + LN + rna-preround unchanged from round 9.
// ---------------------------------------------------------------------------

#define B_  32
#define S_  512
#define D_  1024
#define H_  16
#define DK_ 64
#define F_  4096
#define M_  (B_ * S_)          // 16384 rows

// -------------------- scratch (device globals; no allocs) ------------------
__device__ float g_q    [M_ * D_];
__device__ float g_k    [M_ * D_];
__device__ float g_v    [M_ * D_];
__device__ float g_ctx  [M_ * D_];
__device__ float g_attn [M_ * D_];
__device__ float g_out1 [M_ * D_];
__device__ float g_out1r[M_ * D_];
__device__ float g_ffn  [M_ * D_];
__device__ float g_h    [M_ * F_];
__device__ float g_xr   [M_ * D_];
__device__ float g_wqr  [D_ * D_];
__device__ float g_wkr  [D_ * D_];
__device__ float g_wvr  [D_ * D_];
__device__ float g_wor  [D_ * D_];
__device__ float g_w1r  [D_ * F_];
__device__ float g_w2r  [F_ * D_];

// ---------------------------------------------------------------------------
// Helpers
// ---------------------------------------------------------------------------
__device__ __forceinline__ float gelu_erf_f(float x) {
    return 0.5f * x * (1.0f + erff(x * 0.70710678118654752f));
}
__device__ __forceinline__ float tf32r(float f) {
    uint32_t u;
    asm("cvt.rna.tf32.f32 %0, %1;" : "=r"(u) : "f"(f));
    return __uint_as_float(u);
}
__device__ __forceinline__ uint32_t smem_u32(const void* p) {
    uint32_t a;
    asm("{ .reg .u64 t; cvta.to.shared.u64 t, %1; cvt.u32.u64 %0, t; }"
        : "=r"(a) : "l"(p));
    return a;
}
__device__ __forceinline__ void cp16(uint32_t s, const void* g) {
    asm volatile("cp.async.cg.shared.global [%0], [%1], 16;" :: "r"(s), "l"(g));
}
__device__ __forceinline__ void cp_commit() {
    asm volatile("cp.async.commit_group;" ::: "memory");
}
template <int N>
__device__ __forceinline__ void cp_wait() {
    asm volatile("cp.async.wait_group %0;" :: "n"(N) : "memory");
}
__device__ __forceinline__ void mma_tf32(float c[4],
                                         uint32_t a0, uint32_t a1, uint32_t a2, uint32_t a3,
                                         uint32_t b0, uint32_t b1) {
    asm volatile(
        "mma.sync.aligned.m16n8k8.row.col.f32.tf32.tf32.f32 "
        "{%0,%1,%2,%3}, {%4,%5,%6,%7}, {%8,%9}, {%0,%1,%2,%3};\n"
        : "+f"(c[0]), "+f"(c[1]), "+f"(c[2]), "+f"(c[3])
        : "r"(a0), "r"(a1), "r"(a2), "r"(a3), "r"(b0), "r"(b1));
}

// ---------------------------------------------------------------------------
// Preprocess: Y = tf32_rna(X)
// ---------------------------------------------------------------------------
__global__ void rnd_kernel(const float* __restrict__ X, float* __restrict__ Y,
                           int n4) {
    int i = blockIdx.x * blockDim.x + threadIdx.x;
    if (i < n4) {
        float4 v = ((const float4*)X)[i];
        v.x = tf32r(v.x); v.y = tf32r(v.y); v.z = tf32r(v.z); v.w = tf32r(v.w);
        ((float4*)Y)[i] = v;
    }
}

// ---------------------------------------------------------------------------
// Persistent dual-pipe GEMM: C[M,N] = act(A[M,K] @ W[K,N] + bias[N])
// 296 CTAs x 256 threads. bid<148: HMMA engine; bid>=148: FFMA engine.
// Tiles 128x128, BK=16, 4-stage cp.async. FFMA partition = last 1/4 tiles.
// ---------------------------------------------------------------------------
#define ASTR 20
#define BSTR 136
#define STG_FLT (128 * ASTR + 16 * BSTR)   // 4736
#define GEMM_SMEM (4 * STG_FLT * 4)        // 75776 bytes
#define NSM 148

template <int ACT, int ROUND>
__global__ __launch_bounds__(256, 2) void pd_gemm(
    const float* __restrict__ A, const float* __restrict__ W,
    const float* __restrict__ bias, float* __restrict__ C,
    int N, int K, int nbx, int ntiles)
{
    extern __shared__ float sm[];

    const int tid = threadIdx.x;
    const bool hm = ((int)blockIdx.x < NSM);
    const int idx = hm ? (int)blockIdx.x : (int)blockIdx.x - NSM;
    const int Tf = ntiles >> 2;            // FFMA partition size (1/4)
    const int Th = ntiles - Tf;            // HMMA partition size (3/4)
    const int t0   = hm ? idx : Th + idx;
    const int tend = hm ? Th  : ntiles;

    const int nk = K >> 4;

    // cp.async producer mapping (both engines)
    const int arr = tid >> 1, ak = (tid & 1) * 8;
    const int bkr = tid >> 4, bn = (tid & 15) * 8;
    const uint32_t sA0 = smem_u32(sm) + (uint32_t)(arr * ASTR + ak) * 4u;
    const uint32_t sB0 = smem_u32(sm) + (uint32_t)(128 * ASTR + bkr * BSTR + bn) * 4u;

    for (int t = t0; t < tend; t += NSM) {
        const int bx = t % nbx, by = t / nbx;
        const float* Ag = A + (size_t)(by * 128 + arr) * K + ak;
        const float* Bg = W + (size_t)bkr * N + bx * 128 + bn;

        __syncthreads();   // all warps done with smem from previous tile

        // prologue
        #pragma unroll
        for (int p = 0; p < 3; p++) {
            const uint32_t so = (uint32_t)p * (STG_FLT * 4u);
            const float* ap = Ag + p * 16;
            const float* bp = Bg + (size_t)(p * 16) * N;
            cp16(sA0 + so,      ap);
            cp16(sA0 + so + 16, ap + 4);
            cp16(sB0 + so,      bp);
            cp16(sB0 + so + 16, bp + 4);
            cp_commit();
        }

        if (hm) {
            // ================= HMMA engine (tensor pipe) =================
            const int wid = tid >> 5, lane = tid & 31;
            const int wm = (wid >> 2) * 64;
            const int wn = (wid & 3) * 32;
            const int g  = lane >> 2;
            const int q  = lane & 3;

            float acc[4][4][4];
            #pragma unroll
            for (int mi = 0; mi < 4; mi++)
                #pragma unroll
                for (int nj = 0; nj < 4; nj++)
                    #pragma unroll
                    for (int r = 0; r < 4; r++) acc[mi][nj][r] = 0.f;

            for (int kt = 0; kt < nk; ++kt) {
                if (kt + 2 < nk) cp_wait<2>(); else cp_wait<0>();
                __syncthreads();
                if (kt + 3 < nk) {
                    const uint32_t so = (uint32_t)((kt + 3) & 3) * (STG_FLT * 4u);
                    const float* ap = Ag + (kt + 3) * 16;
                    const float* bp = Bg + (size_t)((kt + 3) * 16) * N;
                    cp16(sA0 + so,      ap);
                    cp16(sA0 + so + 16, ap + 4);
                    cp16(sB0 + so,      bp);
                    cp16(sB0 + so + 16, bp + 4);
                    cp_commit();
                }

                const uint32_t* As32 = (const uint32_t*)(sm + (kt & 3) * STG_FLT);
                const uint32_t* Bs32 = As32 + 128 * ASTR;

                #pragma unroll
                for (int ks = 0; ks < 2; ++ks) {
                    const int k0 = ks * 8;
                    uint32_t a[4][4], b[4][2];
                    #pragma unroll
                    for (int mi = 0; mi < 4; mi++) {
                        const int m0 = wm + mi * 16 + g;
                        a[mi][0] = As32[(m0    ) * ASTR + k0 + q];
                        a[mi][1] = As32[(m0 + 8) * ASTR + k0 + q];
                        a[mi][2] = As32[(m0    ) * ASTR + k0 + q + 4];
                        a[mi][3] = As32[(m0 + 8) * ASTR + k0 + q + 4];
                    }
                    #pragma unroll
                    for (int nj = 0; nj < 4; nj++) {
                        const int n0 = wn + nj * 8 + g;
                        b[nj][0] = Bs32[(k0 + q    ) * BSTR + n0];
                        b[nj][1] = Bs32[(k0 + q + 4) * BSTR + n0];
                    }
                    #pragma unroll
                    for (int mi = 0; mi < 4; mi++)
                        #pragma unroll
                        for (int nj = 0; nj < 4; nj++)
                            mma_tf32(acc[mi][nj], a[mi][0], a[mi][1], a[mi][2], a[mi][3],
                                     b[nj][0], b[nj][1]);
                }
            }

            #pragma unroll
            for (int nj = 0; nj < 4; nj++) {
                const int col = bx * 128 + wn + nj * 8 + 2 * q;
                const float2 bb = *(const float2*)&bias[col];
                #pragma unroll
                for (int mi = 0; mi < 4; mi++) {
                    const int row0 = by * 128 + wm + mi * 16 + g;
                    float2 o0, o1;
                    o0.x = acc[mi][nj][0] + bb.x;
                    o0.y = acc[mi][nj][1] + bb.y;
                    o1.x = acc[mi][nj][2] + bb.x;
                    o1.y = acc[mi][nj][3] + bb.y;
                    if (ACT == 1) {
                        o0.x = gelu_erf_f(o0.x); o0.y = gelu_erf_f(o0.y);
                        o1.x = gelu_erf_f(o1.x); o1.y = gelu_erf_f(o1.y);
                    }
                    if (ROUND == 1) {
                        o0.x = tf32r(o0.x); o0.y = tf32r(o0.y);
                        o1.x = tf32r(o1.x); o1.y = tf32r(o1.y);
                    }
                    *(float2*)&C[(size_t)row0 * N + col]       = o0;
                    *(float2*)&C[(size_t)(row0 + 8) * N + col] = o1;
                }
            }
        } else {
            // ================= FFMA engine (FMA pipe) =================
            const int ty = tid >> 4, tx = tid & 15;   // 8x8 per thread

            float acc[8][8];
            #pragma unroll
            for (int i = 0; i < 8; i++)
                #pragma unroll
                for (int j = 0; j < 8; j++) acc[i][j] = 0.f;

            for (int kt = 0; kt < nk; ++kt) {
                if (kt + 2 < nk) cp_wait<2>(); else cp_wait<0>();
                __syncthreads();
                if (kt + 3 < nk) {
                    const uint32_t so = (uint32_t)((kt + 3) & 3) * (STG_FLT * 4u);
                    const float* ap = Ag + (kt + 3) * 16;
                    const float* bp = Bg + (size_t)((kt + 3) * 16) * N;
                    cp16(sA0 + so,      ap);
                    cp16(sA0 + so + 16, ap + 4);
                    cp16(sB0 + so,      bp);
                    cp16(sB0 + so + 16, bp + 4);
                    cp_commit();
                }

                const float* As = sm + (kt & 3) * STG_FLT;
                const float* Bs = As + 128 * ASTR;

                #pragma unroll
                for (int k = 0; k < 16; ++k) {
                    float a[8], b[8];
                    #pragma unroll
                    for (int i = 0; i < 8; i++)
                        a[i] = As[(ty * 8 + i) * ASTR + k];
                    *(float4*)&b[0] = *(const float4*)&Bs[k * BSTR + tx * 8];
                    *(float4*)&b[4] = *(const float4*)&Bs[k * BSTR + tx * 8 + 4];
                    #pragma unroll
                    for (int i = 0; i < 8; i++)
                        #pragma unroll
                        for (int j = 0; j < 8; j++)
                            acc[i][j] += a[i] * b[j];
                }
            }

            const int col0 = bx * 128 + tx * 8;
            #pragma unroll
            for (int i = 0; i < 8; i++) {
                const int row = by * 128 + ty * 8 + i;
                float o[8];
                #pragma unroll
                for (int j = 0; j < 8; j++) {
                    float vv = acc[i][j] + bias[col0 + j];
                    if (ACT == 1) vv = gelu_erf_f(vv);
                    if (ROUND == 1) vv = tf32r(vv);
                    o[j] = vv;
                }
                *(float4*)&C[(size_t)row * N + col0]     = *(float4*)&o[0];
                *(float4*)&C[(size_t)row * N + col0 + 4] = *(float4*)&o[4];
            }
        }
    }
}

// ---------------------------------------------------------------------------
// Fused attention: grid (S/64, H, B), 512 threads (16 warps). (round-9)
// ---------------------------------------------------------------------------
#define SC_STRIDE 516
#define QK_STRIDE 68

__global__ __launch_bounds__(512) void attention_kernel(
    const float* __restrict__ Q, const float* __restrict__ K,
    const float* __restrict__ V, const int* __restrict__ mask,
    const float* __restrict__ adj, float* __restrict__ ctx)
{
    extern __shared__ float smem[];
    float* sc = smem;
    float* qs = sc + 64 * SC_STRIDE;
    float* kv = qs + 64 * QK_STRIDE;

    const int t  = threadIdx.x;
    const int qt = blockIdx.x, h = blockIdx.y, b = blockIdx.z;
    const int qbase = b * S_ + qt * 64;

    #pragma unroll
    for (int i = 0; i < 2; i++) {
        int lin = t + i * 512;
        int r = lin >> 4, c4 = (lin & 15) << 2;
        float4 qv = *(const float4*)&Q[(size_t)(qbase + r) * D_ + h * DK_ + c4];
        qv.x *= 0.125f; qv.y *= 0.125f; qv.z *= 0.125f; qv.w *= 0.125f;
        *(float4*)&qs[r * QK_STRIDE + c4] = qv;
    }

    const int qi  = t >> 3;
    const int kj0 = (t & 7) << 3;
    const int qg  = qt * 64 + qi;

    for (int kt = 0; kt < 8; ++kt) {
        __syncthreads();
        #pragma unroll
        for (int i = 0; i < 2; i++) {
            int lin = t + i * 512;
            int r = lin >> 4, c4 = (lin & 15) << 2;
            float4 kk = *(const float4*)&K[(size_t)(b * S_ + kt * 64 + r) * D_ + h * DK_ + c4];
            kv[(c4 + 0) * QK_STRIDE + r] = kk.x;
            kv[(c4 + 1) * QK_STRIDE + r] = kk.y;
            kv[(c4 + 2) * QK_STRIDE + r] = kk.z;
            kv[(c4 + 3) * QK_STRIDE + r] = kk.w;
        }
        __syncthreads();

        float acc[8];
        #pragma unroll
        for (int j = 0; j < 8; j++) acc[j] = 0.f;

        #pragma unroll
        for (int d = 0; d < 64; ++d) {
            float qv = qs[qi * QK_STRIDE + d];
            const float4* kr = (const float4*)&kv[d * QK_STRIDE + kj0];
            float4 k0 = kr[0], k1 = kr[1];
            acc[0] += qv * k0.x; acc[1] += qv * k0.y; acc[2] += qv * k0.z; acc[3] += qv * k0.w;
            acc[4] += qv * k1.x; acc[5] += qv * k1.y; acc[6] += qv * k1.z; acc[7] += qv * k1.w;
        }

        const float* adjr = &adj[((size_t)(b * S_ + qg)) * S_ + kt * 64 + kj0];
        const int*   mr   = &mask[b * S_ + kt * 64 + kj0];
        float*       scr  = &sc[qi * SC_STRIDE + kt * 64 + kj0];
        #pragma unroll
        for (int j = 0; j < 8; j++)
            scr[j] = acc[j] + (float)mr[j] * -1e9f + adjr[j];
    }
    __syncthreads();

    {
        const int warp = t >> 5, lane = t & 31;
        for (int row = warp; row < 64; row += 16) {
            float* r = &sc[row * SC_STRIDE];
            float mx = -3.0e38f;
            #pragma unroll
            for (int i = 0; i < 16; i++) mx = fmaxf(mx, r[lane + 32 * i]);
            #pragma unroll
            for (int o = 16; o; o >>= 1) mx = fmaxf(mx, __shfl_xor_sync(0xffffffffu, mx, o));
            float e[16], sum = 0.f;
            #pragma unroll
            for (int i = 0; i < 16; i++) { e[i] = __expf(r[lane + 32 * i] - mx); sum += e[i]; }
            #pragma unroll
            for (int o = 16; o; o >>= 1) sum += __shfl_xor_sync(0xffffffffu, sum, o);
            const float inv = 1.0f / sum;
            #pragma unroll
            for (int i = 0; i < 16; i++) r[lane + 32 * i] = e[i] * inv;
        }
    }

    const int dc0 = kj0;
    float acc[8];
    #pragma unroll
    for (int j = 0; j < 8; j++) acc[j] = 0.f;

    for (int kt = 0; kt < 8; ++kt) {
        __syncthreads();
        #pragma unroll
        for (int i = 0; i < 2; i++) {
            int lin = t + i * 512;
            int r = lin >> 4, c4 = (lin & 15) << 2;
            float4 vv = *(const float4*)&V[(size_t)(b * S_ + kt * 64 + r) * D_ + h * DK_ + c4];
            *(float4*)&kv[r * QK_STRIDE + c4] = vv;
        }
        __syncthreads();

        #pragma unroll
        for (int kk = 0; kk < 64; ++kk) {
            float p = sc[qi * SC_STRIDE + kt * 64 + kk];
            const float4* vr = (const float4*)&kv[kk * QK_STRIDE + dc0];
            float4 v0 = vr[0], v1 = vr[1];
            acc[0] += p * v0.x; acc[1] += p * v0.y; acc[2] += p * v0.z; acc[3] += p * v0.w;
            acc[4] += p * v1.x; acc[5] += p * v1.y; acc[6] += p * v1.z; acc[7] += p * v1.w;
        }
    }

    float* outp = &ctx[(size_t)(qbase + qi) * D_ + h * DK_ + dc0];
    float4 o0, o1;
    o0.x = tf32r(acc[0]); o0.y = tf32r(acc[1]); o0.z = tf32r(acc[2]); o0.w = tf32r(acc[3]);
    o1.x = tf32r(acc[4]); o1.y = tf32r(acc[5]); o1.z = tf32r(acc[6]); o1.w = tf32r(acc[7]);
    *(float4*)&outp[0] = o0;
    *(float4*)&outp[4] = o1;
}

// ---------------------------------------------------------------------------
// Residual + LayerNorm; optional tf32-rounded secondary output
// ---------------------------------------------------------------------------
__device__ __forceinline__ float blockReduceSum(float val, float* shared) {
    const int lane = threadIdx.x & 31, wid = threadIdx.x >> 5;
    #pragma unroll
    for (int o = 16; o; o >>= 1) val += __shfl_xor_sync(0xffffffffu, val, o);
    __syncthreads();
    if (lane == 0) shared[wid] = val;
    __syncthreads();
    float r = shared[0];
    #pragma unroll
    for (int w = 1; w < 8; w++) r += shared[w];
    return r;
}

template <int WR>
__global__ __launch_bounds__(256) void ln_residual_kernel(
    const float* __restrict__ A, const float* __restrict__ Bm,
    const float* __restrict__ gamma, const float* __restrict__ beta,
    float* __restrict__ out, float* __restrict__ outR)
{
    __shared__ float red[8];
    const int row = blockIdx.x;
    const int tid = threadIdx.x;
    const size_t base = (size_t)row * D_;

    float v[4];
    float s = 0.f;
    #pragma unroll
    for (int i = 0; i < 4; i++) {
        int c = tid + 256 * i;
        v[i] = A[base + c] + Bm[base + c];
        s += v[i];
    }
    s = blockReduceSum(s, red);
    const float mean = s * (1.0f / (float)D_);

    float s2 = 0.f;
    #pragma unroll
    for (int i = 0; i < 4; i++) { float d = v[i] - mean; s2 += d * d; }
    s2 = blockReduceSum(s2, red);

    const float stdv = sqrtf(s2 * (1.0f / (float)(D_ - 1)));   // ddof=1
    const float inv  = 1.0f / (stdv + 1e-6f);                  // /(std+eps)

    #pragma unroll
    for (int i = 0; i < 4; i++) {
        int c = tid + 256 * i;
        float o = gamma[c] * (v[i] - mean) * inv + beta[c];
        out[base + c] = o;
        if (WR) outR[base + c] = tf32r(o);
    }
}

// ---------------------------------------------------------------------------
// launch
// ---------------------------------------------------------------------------
extern "C" void kernel_launch(void* const* d_in, const int* in_sizes, int n_in,
                              void* d_out, int out_size)
{
    const float* x    = (const float*)d_in[0];
    const int*   mask = (const int*)  d_in[1];
    const float* adj  = (const float*)d_in[2];
    const float* Wq = (const float*)d_in[4];  const float* bq = (const float*)d_in[5];
    const float* Wk = (const float*)d_in[6];  const float* bk = (const float*)d_in[7];
    const float* Wv = (const float*)d_in[8];  const float* bv = (const float*)d_in[9];
    const float* Wo = (const float*)d_in[10]; const float* bo = (const float*)d_in[11];
    const float* W1 = (const float*)d_in[12]; const float* b1 = (const float*)d_in[13];
    const float* W2 = (const float*)d_in[14]; const float* b2 = (const float*)d_in[15];
    const float* gamma = (const float*)d_in[16];
    const float* beta  = (const float*)d_in[17];
    float* out = (float*)d_out;

    float *q, *k, *v, *ctx, *attn, *out1, *out1r, *ffn, *hbuf;
    float *xr, *wqr, *wkr, *wvr, *wor, *w1r, *w2r;
    cudaGetSymbolAddress((void**)&q,     g_q);
    cudaGetSymbolAddress((void**)&k,     g_k);
    cudaGetSymbolAddress((void**)&v,     g_v);
    cudaGetSymbolAddress((void**)&ctx,   g_ctx);
    cudaGetSymbolAddress((void**)&attn,  g_attn);
    cudaGetSymbolAddress((void**)&out1,  g_out1);
    cudaGetSymbolAddress((void**)&out1r, g_out1r);
    cudaGetSymbolAddress((void**)&ffn,   g_ffn);
    cudaGetSymbolAddress((void**)&hbuf,  g_h);
    cudaGetSymbolAddress((void**)&xr,    g_xr);
    cudaGetSymbolAddress((void**)&wqr,   g_wqr);
    cudaGetSymbolAddress((void**)&wkr,   g_wkr);
    cudaGetSymbolAddress((void**)&wvr,   g_wvr);
    cudaGetSymbolAddress((void**)&wor,   g_wor);
    cudaGetSymbolAddress((void**)&w1r,   g_w1r);
    cudaGetSymbolAddress((void**)&w2r,   g_w2r);

    cudaFuncSetAttribute(pd_gemm<0,0>,
                         cudaFuncAttributeMaxDynamicSharedMemorySize, GEMM_SMEM);
    cudaFuncSetAttribute(pd_gemm<1,1>,
                         cudaFuncAttributeMaxDynamicSharedMemorySize, GEMM_SMEM);

    const int ATTN_SMEM = (64 * SC_STRIDE + 2 * 64 * QK_STRIDE) * (int)sizeof(float);
    cudaFuncSetAttribute(attention_kernel,
                         cudaFuncAttributeMaxDynamicSharedMemorySize, ATTN_SMEM);

    // ---- preprocessing: rna-round GEMM operands ----
    rnd_kernel<<<(M_ * D_ / 4 + 255) / 256, 256>>>(x,  xr,  M_ * D_ / 4);
    rnd_kernel<<<(D_ * D_ / 4 + 255) / 256, 256>>>(Wq, wqr, D_ * D_ / 4);
    rnd_kernel<<<(D_ * D_ / 4 + 255) / 256, 256>>>(Wk, wkr, D_ * D_ / 4);
    rnd_kernel<<<(D_ * D_ / 4 + 255) / 256, 256>>>(Wv, wvr, D_ * D_ / 4);
    rnd_kernel<<<(D_ * D_ / 4 + 255) / 256, 256>>>(Wo, wor, D_ * D_ / 4);
    rnd_kernel<<<(D_ * F_ / 4 + 255) / 256, 256>>>(W1, w1r, D_ * F_ / 4);
    rnd_kernel<<<(F_ * D_ / 4 + 255) / 256, 256>>>(W2, w2r, F_ * D_ / 4);

    const int nbxD = D_ / 128, ntD = nbxD * (M_ / 128);   // 8, 1024
    const int nbxF = F_ / 128, ntF = nbxF * (M_ / 128);   // 32, 4096

    // QKV projections
    pd_gemm<0,0><<<2 * NSM, 256, GEMM_SMEM>>>(xr, wqr, bq, q, D_, D_, nbxD, ntD);
    pd_gemm<0,0><<<2 * NSM, 256, GEMM_SMEM>>>(xr, wkr, bk, k, D_, D_, nbxD, ntD);
    pd_gemm<0,0><<<2 * NSM, 256, GEMM_SMEM>>>(xr, wvr, bv, v, D_, D_, nbxD, ntD);

    // attention (fp32 compute; emits rounded ctx)
    dim3 gA(S_ / 64, H_, B_);
    attention_kernel<<<gA, 512, ATTN_SMEM>>>(q, k, v, mask, adj, ctx);

    // output projection
    pd_gemm<0,0><<<2 * NSM, 256, GEMM_SMEM>>>(ctx, wor, bo, attn, D_, D_, nbxD, ntD);

    // LN1
    ln_residual_kernel<1><<<M_, 256>>>(x, attn, gamma, beta, out1, out1r);

    // FFN
    pd_gemm<1,1><<<2 * NSM, 256, GEMM_SMEM>>>(out1r, w1r, b1, hbuf, F_, D_, nbxF, ntF);
    pd_gemm<0,0><<<2 * NSM, 256, GEMM_SMEM>>>(hbuf, w2r, b2, ffn, D_, F_, nbxD, ntD);

    // LN2
    ln_residual_kernel<0><<<M_, 256>>>(out1, ffn, gamma, beta, out, (float*)0);
}

// round 13
// speedup vs baseline: 2.3786x; 2.0593x over previous
#include <cuda_runtime.h>
#include <stdint.h>
#include <math.h>

// ---------------------------------------------------------------------------
// EncoderLayer: B=32, S=512, D=1024, H=16, dk=64, F=4096
// Round 12: revert to round-9 engine (best: 7274us) + persistent GEMM
// scheduling (296 CTAs, tile-strided; kills wave tails) + fused QKV GEMM
// (N=3072) + corrected cp.async tail waits. Dual-pipe abandoned: legacy
// mma.sync shares throughput with the FMA pipe on sm_103a (r10/r11 evidence).
// ---------------------------------------------------------------------------

#define B_  32
#define S_  512
#define D_  1024
#define H_  16
#define DK_ 64
#define F_  4096
#define M_  (B_ * S_)          // 16384 rows
#define D3_ (3 * D_)           // 3072

// -------------------- scratch (device globals; no allocs) ------------------
__device__ float g_qkv  [M_ * D3_];  // fused Q|K|V, stride 3072
__device__ float g_ctx  [M_ * D_];   // rounded (feeds Wo GEMM)
__device__ float g_attn [M_ * D_];
__device__ float g_out1 [M_ * D_];
__device__ float g_out1r[M_ * D_];   // rounded (feeds FFN1)
__device__ float g_ffn  [M_ * D_];
__device__ float g_h    [M_ * F_];   // rounded (feeds FFN2)
__device__ float g_xr   [M_ * D_];   // rounded x
__device__ float g_wcat [D_ * D3_];  // rounded [Wq|Wk|Wv] concat on N
__device__ float g_bcat [D3_];       // [bq|bk|bv]
__device__ float g_wor  [D_ * D_];
__device__ float g_w1r  [D_ * F_];
__device__ float g_w2r  [F_ * D_];

// ---------------------------------------------------------------------------
// Helpers
// ---------------------------------------------------------------------------
__device__ __forceinline__ float gelu_erf_f(float x) {
    return 0.5f * x * (1.0f + erff(x * 0.70710678118654752f));
}
__device__ __forceinline__ float tf32r(float f) {
    uint32_t u;
    asm("cvt.rna.tf32.f32 %0, %1;" : "=r"(u) : "f"(f));
    return __uint_as_float(u);
}
__device__ __forceinline__ uint32_t smem_u32(const void* p) {
    uint32_t a;
    asm("{ .reg .u64 t; cvta.to.shared.u64 t, %1; cvt.u32.u64 %0, t; }"
        : "=r"(a) : "l"(p));
    return a;
}
__device__ __forceinline__ void cp16(uint32_t s, const void* g) {
    asm volatile("cp.async.cg.shared.global [%0], [%1], 16;" :: "r"(s), "l"(g));
}
__device__ __forceinline__ void cp_commit() {
    asm volatile("cp.async.commit_group;" ::: "memory");
}
template <int N>
__device__ __forceinline__ void cp_wait() {
    asm volatile("cp.async.wait_group %0;" :: "n"(N) : "memory");
}
__device__ __forceinline__ void mma_tf32(float c[4],
                                         uint32_t a0, uint32_t a1, uint32_t a2, uint32_t a3,
                                         uint32_t b0, uint32_t b1) {
    asm volatile(
        "mma.sync.aligned.m16n8k8.row.col.f32.tf32.tf32.f32 "
        "{%0,%1,%2,%3}, {%4,%5,%6,%7}, {%8,%9}, {%0,%1,%2,%3};\n"
        : "+f"(c[0]), "+f"(c[1]), "+f"(c[2]), "+f"(c[3])
        : "r"(a0), "r"(a1), "r"(a2), "r"(a3), "r"(b0), "r"(b1));
}

// ---------------------------------------------------------------------------
// Preprocess kernels
// ---------------------------------------------------------------------------
__global__ void rnd_kernel(const float* __restrict__ X, float* __restrict__ Y,
                           int n4) {
    int i = blockIdx.x * blockDim.x + threadIdx.x;
    if (i < n4) {
        float4 v = ((const float4*)X)[i];
        v.x = tf32r(v.x); v.y = tf32r(v.y); v.z = tf32r(v.z); v.w = tf32r(v.w);
        ((float4*)Y)[i] = v;
    }
}

// round W[D,D] into wcat[D,3072] at column offset slot*1024
__global__ void rnd_cat_kernel(const float* __restrict__ W,
                               float* __restrict__ Wcat, int slot) {
    int i = blockIdx.x * blockDim.x + threadIdx.x;   // over D*D/4
    if (i < D_ * D_ / 4) {
        float4 v = ((const float4*)W)[i];
        v.x = tf32r(v.x); v.y = tf32r(v.y); v.z = tf32r(v.z); v.w = tf32r(v.w);
        int e = i * 4;
        int row = e >> 10, col = e & 1023;
        ((float4*)Wcat)[(row * D3_ + slot * D_ + col) >> 2] = v;
    }
}

__global__ void bias_cat_kernel(const float* __restrict__ b0,
                                const float* __restrict__ b1,
                                const float* __restrict__ b2,
                                float* __restrict__ bc) {
    int i = blockIdx.x * blockDim.x + threadIdx.x;
    if (i < D3_) {
        float v = (i < D_) ? b0[i] : (i < 2 * D_) ? b1[i - D_] : b2[i - 2 * D_];
        bc[i] = v;
    }
}

// ---------------------------------------------------------------------------
// Persistent tf32 GEMM: C[M,N] = act(A[M,K] @ W[K,N] + bias[N])
// 296 CTAs x 256 threads, tile-strided. Tiles 128x128, BK=16, 4-stage
// cp.async with corrected tail waits. Warp tile 64x32 (2x4 warps).
// ---------------------------------------------------------------------------
#define ASTR 20
#define BSTR 136
#define STG_FLT (128 * ASTR + 16 * BSTR)   // 4736
#define GEMM_SMEM (4 * STG_FLT * 4)        // 75776 bytes
#define NPC 296

template <int ACT, int ROUND>
__global__ __launch_bounds__(256, 2) void pers_gemm(
    const float* __restrict__ A, const float* __restrict__ W,
    const float* __restrict__ bias, float* __restrict__ C,
    int N, int K, int nbx, int ntiles)
{
    extern __shared__ float sm[];

    const int tid = threadIdx.x;
    const int wid = tid >> 5, lane = tid & 31;
    const int wm = (wid >> 2) * 64;
    const int wn = (wid & 3) * 32;
    const int g  = lane >> 2;
    const int q  = lane & 3;
    const int nk = K >> 4;

    const int arr = tid >> 1, ak = (tid & 1) * 8;
    const int bkr = tid >> 4, bn = (tid & 15) * 8;
    const uint32_t sA0 = smem_u32(sm) + (uint32_t)(arr * ASTR + ak) * 4u;
    const uint32_t sB0 = smem_u32(sm) + (uint32_t)(128 * ASTR + bkr * BSTR + bn) * 4u;

    for (int t = blockIdx.x; t < ntiles; t += NPC) {
        const int bx = t % nbx, by = t / nbx;
        const float* Ag = A + (size_t)(by * 128 + arr) * K + ak;
        const float* Bg = W + (size_t)bkr * N + bx * 128 + bn;

        __syncthreads();   // all warps done reading smem of previous tile

        #pragma unroll
        for (int p = 0; p < 3; p++) {
            const uint32_t so = (uint32_t)p * (STG_FLT * 4u);
            cp16(sA0 + so,      Ag + p * 16);
            cp16(sA0 + so + 16, Ag + p * 16 + 4);
            cp16(sB0 + so,      Bg + (size_t)(p * 16) * N);
            cp16(sB0 + so + 16, Bg + (size_t)(p * 16) * N + 4);
            cp_commit();
        }

        float acc[4][4][4];
        #pragma unroll
        for (int mi = 0; mi < 4; mi++)
            #pragma unroll
            for (int nj = 0; nj < 4; nj++)
                #pragma unroll
                for (int r = 0; r < 4; r++) acc[mi][nj][r] = 0.f;

        for (int kt = 0; kt < nk; ++kt) {
            if (kt + 2 < nk) cp_wait<2>(); else cp_wait<0>();
            __syncthreads();
            if (kt + 3 < nk) {
                const uint32_t so = (uint32_t)((kt + 3) & 3) * (STG_FLT * 4u);
                cp16(sA0 + so,      Ag + (kt + 3) * 16);
                cp16(sA0 + so + 16, Ag + (kt + 3) * 16 + 4);
                cp16(sB0 + so,      Bg + (size_t)((kt + 3) * 16) * N);
                cp16(sB0 + so + 16, Bg + (size_t)((kt + 3) * 16) * N + 4);
                cp_commit();
            }

            const uint32_t* As32 = (const uint32_t*)(sm + (kt & 3) * STG_FLT);
            const uint32_t* Bs32 = As32 + 128 * ASTR;

            #pragma unroll
            for (int ks = 0; ks < 2; ++ks) {
                const int k0 = ks * 8;
                uint32_t a[4][4], b[4][2];
                #pragma unroll
                for (int mi = 0; mi < 4; mi++) {
                    const int m0 = wm + mi * 16 + g;
                    a[mi][0] = As32[(m0    ) * ASTR + k0 + q];
                    a[mi][1] = As32[(m0 + 8) * ASTR + k0 + q];
                    a[mi][2] = As32[(m0    ) * ASTR + k0 + q + 4];
                    a[mi][3] = As32[(m0 + 8) * ASTR + k0 + q + 4];
                }
                #pragma unroll
                for (int nj = 0; nj < 4; nj++) {
                    const int n0 = wn + nj * 8 + g;
                    b[nj][0] = Bs32[(k0 + q    ) * BSTR + n0];
                    b[nj][1] = Bs32[(k0 + q + 4) * BSTR + n0];
                }
                #pragma unroll
                for (int mi = 0; mi < 4; mi++)
                    #pragma unroll
                    for (int nj = 0; nj < 4; nj++)
                        mma_tf32(acc[mi][nj], a[mi][0], a[mi][1], a[mi][2], a[mi][3],
                                 b[nj][0], b[nj][1]);
            }
        }

        #pragma unroll
        for (int nj = 0; nj < 4; nj++) {
            const int col = bx * 128 + wn + nj * 8 + 2 * q;
            const float2 bb = *(const float2*)&bias[col];
            #pragma unroll
            for (int mi = 0; mi < 4; mi++) {
                const int row0 = by * 128 + wm + mi * 16 + g;
                float2 o0, o1;
                o0.x = acc[mi][nj][0] + bb.x;
                o0.y = acc[mi][nj][1] + bb.y;
                o1.x = acc[mi][nj][2] + bb.x;
                o1.y = acc[mi][nj][3] + bb.y;
                if (ACT == 1) {
                    o0.x = gelu_erf_f(o0.x); o0.y = gelu_erf_f(o0.y);
                    o1.x = gelu_erf_f(o1.x); o1.y = gelu_erf_f(o1.y);
                }
                if (ROUND == 1) {
                    o0.x = tf32r(o0.x); o0.y = tf32r(o0.y);
                    o1.x = tf32r(o1.x); o1.y = tf32r(o1.y);
                }
                *(float2*)&C[(size_t)row0 * N + col]       = o0;
                *(float2*)&C[(size_t)(row0 + 8) * N + col] = o1;
            }
        }
    }
}

// ---------------------------------------------------------------------------
// Fused attention: grid (S/64, H, B), 512 threads. Reads fused QKV buffer
// (stride 3072: Q at +0, K at +1024, V at +2048). Emits rounded ctx.
// ---------------------------------------------------------------------------
#define SC_STRIDE 516
#define QK_STRIDE 68

__global__ __launch_bounds__(512) void attention_kernel(
    const float* __restrict__ QKV, const int* __restrict__ mask,
    const float* __restrict__ adj, float* __restrict__ ctx)
{
    extern __shared__ float smem[];
    float* sc = smem;
    float* qs = sc + 64 * SC_STRIDE;
    float* kv = qs + 64 * QK_STRIDE;

    const int t  = threadIdx.x;
    const int qt = blockIdx.x, h = blockIdx.y, b = blockIdx.z;
    const int qbase = b * S_ + qt * 64;

    #pragma unroll
    for (int i = 0; i < 2; i++) {
        int lin = t + i * 512;
        int r = lin >> 4, c4 = (lin & 15) << 2;
        float4 qv = *(const float4*)&QKV[(size_t)(qbase + r) * D3_ + h * DK_ + c4];
        qv.x *= 0.125f; qv.y *= 0.125f; qv.z *= 0.125f; qv.w *= 0.125f;
        *(float4*)&qs[r * QK_STRIDE + c4] = qv;
    }

    const int qi  = t >> 3;
    const int kj0 = (t & 7) << 3;
    const int qg  = qt * 64 + qi;

    for (int kt = 0; kt < 8; ++kt) {
        __syncthreads();
        #pragma unroll
        for (int i = 0; i < 2; i++) {
            int lin = t + i * 512;
            int r = lin >> 4, c4 = (lin & 15) << 2;
            float4 kk = *(const float4*)&QKV[(size_t)(b * S_ + kt * 64 + r) * D3_ + D_ + h * DK_ + c4];
            kv[(c4 + 0) * QK_STRIDE + r] = kk.x;
            kv[(c4 + 1) * QK_STRIDE + r] = kk.y;
            kv[(c4 + 2) * QK_STRIDE + r] = kk.z;
            kv[(c4 + 3) * QK_STRIDE + r] = kk.w;
        }
        __syncthreads();

        float acc[8];
        #pragma unroll
        for (int j = 0; j < 8; j++) acc[j] = 0.f;

        #pragma unroll
        for (int d = 0; d < 64; ++d) {
            float qv = qs[qi * QK_STRIDE + d];
            const float4* kr = (const float4*)&kv[d * QK_STRIDE + kj0];
            float4 k0 = kr[0], k1 = kr[1];
            acc[0] += qv * k0.x; acc[1] += qv * k0.y; acc[2] += qv * k0.z; acc[3] += qv * k0.w;
            acc[4] += qv * k1.x; acc[5] += qv * k1.y; acc[6] += qv * k1.z; acc[7] += qv * k1.w;
        }

        const float* adjr = &adj[((size_t)(b * S_ + qg)) * S_ + kt * 64 + kj0];
        const int*   mr   = &mask[b * S_ + kt * 64 + kj0];
        float*       scr  = &sc[qi * SC_STRIDE + kt * 64 + kj0];
        #pragma unroll
        for (int j = 0; j < 8; j++)
            scr[j] = acc[j] + (float)mr[j] * -1e9f + adjr[j];
    }
    __syncthreads();

    {
        const int warp = t >> 5, lane = t & 31;
        for (int row = warp; row < 64; row += 16) {
            float* r = &sc[row * SC_STRIDE];
            float mx = -3.0e38f;
            #pragma unroll
            for (int i = 0; i < 16; i++) mx = fmaxf(mx, r[lane + 32 * i]);
            #pragma unroll
            for (int o = 16; o; o >>= 1) mx = fmaxf(mx, __shfl_xor_sync(0xffffffffu, mx, o));
            float e[16], sum = 0.f;
            #pragma unroll
            for (int i = 0; i < 16; i++) { e[i] = __expf(r[lane + 32 * i] - mx); sum += e[i]; }
            #pragma unroll
            for (int o = 16; o; o >>= 1) sum += __shfl_xor_sync(0xffffffffu, sum, o);
            const float inv = 1.0f / sum;
            #pragma unroll
            for (int i = 0; i < 16; i++) r[lane + 32 * i] = e[i] * inv;
        }
    }

    const int dc0 = kj0;
    float acc[8];
    #pragma unroll
    for (int j = 0; j < 8; j++) acc[j] = 0.f;

    for (int kt = 0; kt < 8; ++kt) {
        __syncthreads();
        #pragma unroll
        for (int i = 0; i < 2; i++) {
            int lin = t + i * 512;
            int r = lin >> 4, c4 = (lin & 15) << 2;
            float4 vv = *(const float4*)&QKV[(size_t)(b * S_ + kt * 64 + r) * D3_ + 2 * D_ + h * DK_ + c4];
            *(float4*)&kv[r * QK_STRIDE + c4] = vv;
        }
        __syncthreads();

        #pragma unroll
        for (int kk = 0; kk < 64; ++kk) {
            float p = sc[qi * SC_STRIDE + kt * 64 + kk];
            const float4* vr = (const float4*)&kv[kk * QK_STRIDE + dc0];
            float4 v0 = vr[0], v1 = vr[1];
            acc[0] += p * v0.x; acc[1] += p * v0.y; acc[2] += p * v0.z; acc[3] += p * v0.w;
            acc[4] += p * v1.x; acc[5] += p * v1.y; acc[6] += p * v1.z; acc[7] += p * v1.w;
        }
    }

    float* outp = &ctx[(size_t)(qbase + qi) * D_ + h * DK_ + dc0];
    float4 o0, o1;
    o0.x = tf32r(acc[0]); o0.y = tf32r(acc[1]); o0.z = tf32r(acc[2]); o0.w = tf32r(acc[3]);
    o1.x = tf32r(acc[4]); o1.y = tf32r(acc[5]); o1.z = tf32r(acc[6]); o1.w = tf32r(acc[7]);
    *(float4*)&outp[0] = o0;
    *(float4*)&outp[4] = o1;
}

// ---------------------------------------------------------------------------
// Residual + LayerNorm; optional tf32-rounded secondary output
// ---------------------------------------------------------------------------
__device__ __forceinline__ float blockReduceSum(float val, float* shared) {
    const int lane = threadIdx.x & 31, wid = threadIdx.x >> 5;
    #pragma unroll
    for (int o = 16; o; o >>= 1) val += __shfl_xor_sync(0xffffffffu, val, o);
    __syncthreads();
    if (lane == 0) shared[wid] = val;
    __syncthreads();
    float r = shared[0];
    #pragma unroll
    for (int w = 1; w < 8; w++) r += shared[w];
    return r;
}

template <int WR>
__global__ __launch_bounds__(256) void ln_residual_kernel(
    const float* __restrict__ A, const float* __restrict__ Bm,
    const float* __restrict__ gamma, const float* __restrict__ beta,
    float* __restrict__ out, float* __restrict__ outR)
{
    __shared__ float red[8];
    const int row = blockIdx.x;
    const int tid = threadIdx.x;
    const size_t base = (size_t)row * D_;

    float v[4];
    float s = 0.f;
    #pragma unroll
    for (int i = 0; i < 4; i++) {
        int c = tid + 256 * i;
        v[i] = A[base + c] + Bm[base + c];
        s += v[i];
    }
    s = blockReduceSum(s, red);
    const float mean = s * (1.0f / (float)D_);

    float s2 = 0.f;
    #pragma unroll
    for (int i = 0; i < 4; i++) { float d = v[i] - mean; s2 += d * d; }
    s2 = blockReduceSum(s2, red);

    const float stdv = sqrtf(s2 * (1.0f / (float)(D_ - 1)));   // ddof=1
    const float inv  = 1.0f / (stdv + 1e-6f);                  // /(std+eps)

    #pragma unroll
    for (int i = 0; i < 4; i++) {
        int c = tid + 256 * i;
        float o = gamma[c] * (v[i] - mean) * inv + beta[c];
        out[base + c] = o;
        if (WR) outR[base + c] = tf32r(o);
    }
}

// ---------------------------------------------------------------------------
// launch
// ---------------------------------------------------------------------------
extern "C" void kernel_launch(void* const* d_in, const int* in_sizes, int n_in,
                              void* d_out, int out_size)
{
    const float* x    = (const float*)d_in[0];
    const int*   mask = (const int*)  d_in[1];
    const float* adj  = (const float*)d_in[2];
    const float* Wq = (const float*)d_in[4];  const float* bq = (const float*)d_in[5];
    const float* Wk = (const float*)d_in[6];  const float* bk = (const float*)d_in[7];
    const float* Wv = (const float*)d_in[8];  const float* bv = (const float*)d_in[9];
    const float* Wo = (const float*)d_in[10]; const float* bo = (const float*)d_in[11];
    const float* W1 = (const float*)d_in[12]; const float* b1 = (const float*)d_in[13];
    const float* W2 = (const float*)d_in[14]; const float* b2 = (const float*)d_in[15];
    const float* gamma = (const float*)d_in[16];
    const float* beta  = (const float*)d_in[17];
    float* out = (float*)d_out;

    float *qkv, *ctx, *attn, *out1, *out1r, *ffn, *hbuf;
    float *xr, *wcat, *bcat, *wor, *w1r, *w2r;
    cudaGetSymbolAddress((void**)&qkv,   g_qkv);
    cudaGetSymbolAddress((void**)&ctx,   g_ctx);
    cudaGetSymbolAddress((void**)&attn,  g_attn);
    cudaGetSymbolAddress((void**)&out1,  g_out1);
    cudaGetSymbolAddress((void**)&out1r, g_out1r);
    cudaGetSymbolAddress((void**)&ffn,   g_ffn);
    cudaGetSymbolAddress((void**)&hbuf,  g_h);
    cudaGetSymbolAddress((void**)&xr,    g_xr);
    cudaGetSymbolAddress((void**)&wcat,  g_wcat);
    cudaGetSymbolAddress((void**)&bcat,  g_bcat);
    cudaGetSymbolAddress((void**)&wor,   g_wor);
    cudaGetSymbolAddress((void**)&w1r,   g_w1r);
    cudaGetSymbolAddress((void**)&w2r,   g_w2r);

    cudaFuncSetAttribute(pers_gemm<0,0>,
                         cudaFuncAttributeMaxDynamicSharedMemorySize, GEMM_SMEM);
    cudaFuncSetAttribute(pers_gemm<1,1>,
                         cudaFuncAttributeMaxDynamicSharedMemorySize, GEMM_SMEM);

    const int ATTN_SMEM = (64 * SC_STRIDE + 2 * 64 * QK_STRIDE) * (int)sizeof(float);
    cudaFuncSetAttribute(attention_kernel,
                         cudaFuncAttributeMaxDynamicSharedMemorySize, ATTN_SMEM);

    // ---- preprocessing: rna-round operands; concat QKV weights/biases ----
    rnd_kernel<<<(M_ * D_ / 4 + 255) / 256, 256>>>(x,  xr,  M_ * D_ / 4);
    rnd_cat_kernel<<<(D_ * D_ / 4 + 255) / 256, 256>>>(Wq, wcat, 0);
    rnd_cat_kernel<<<(D_ * D_ / 4 + 255) / 256, 256>>>(Wk, wcat, 1);
    rnd_cat_kernel<<<(D_ * D_ / 4 + 255) / 256, 256>>>(Wv, wcat, 2);
    bias_cat_kernel<<<(D3_ + 255) / 256, 256>>>(bq, bk, bv, bcat);
    rnd_kernel<<<(D_ * D_ / 4 + 255) / 256, 256>>>(Wo, wor, D_ * D_ / 4);
    rnd_kernel<<<(D_ * F_ / 4 + 255) / 256, 256>>>(W1, w1r, D_ * F_ / 4);
    rnd_kernel<<<(F_ * D_ / 4 + 255) / 256, 256>>>(W2, w2r, F_ * D_ / 4);

    const int nbx3 = D3_ / 128, nt3 = nbx3 * (M_ / 128);   // 24, 3072
    const int nbxD = D_  / 128, ntD = nbxD * (M_ / 128);   // 8, 1024
    const int nbxF = F_  / 128, ntF = nbxF * (M_ / 128);   // 32, 4096

    // fused QKV projection
    pers_gemm<0,0><<<NPC, 256, GEMM_SMEM>>>(xr, wcat, bcat, qkv, D3_, D_, nbx3, nt3);

    // attention (fp32 compute; emits rounded ctx)
    dim3 gA(S_ / 64, H_, B_);
    attention_kernel<<<gA, 512, ATTN_SMEM>>>(qkv, mask, adj, ctx);

    // output projection
    pers_gemm<0,0><<<NPC, 256, GEMM_SMEM>>>(ctx, wor, bo, attn, D_, D_, nbxD, ntD);

    // LN1
    ln_residual_kernel<1><<<M_, 256>>>(x, attn, gamma, beta, out1, out1r);

    // FFN
    pers_gemm<1,1><<<NPC, 256, GEMM_SMEM>>>(out1r, w1r, b1, hbuf, F_, D_, nbxF, ntF);
    pers_gemm<0,0><<<NPC, 256, GEMM_SMEM>>>(hbuf, w2r, b2, ffn, D_, F_, nbxD, ntD);

    // LN2
    ln_residual_kernel<0><<<M_, 256>>>(out1, ffn, gamma, beta, out, (float*)0);
}